// round 8
// baseline (speedup 1.0000x reference)
#include <cuda_runtime.h>
#include <cuda_bf16.h>

#define BATCH 16
#define LEN   2048
#define JT    37              // 37*16 = 592 = 148*4 blocks -> one even wave
#define TPB   256
#define NW    8
#define CHUNK 256             // elements per warp in compaction
#define KPW   8               // ballot sub-iterations per warp
#define GAMMA 0.1f
#define MAXM  56              // max j-slots per block
#define NBLK  (BATCH * JT)

// Scratch (no allocations allowed)
__device__ float g_Px[BATCH][LEN];    // compacted positive x (zero-padded)
__device__ float g_Pf[BATCH][LEN];    // compacted positive f (zero-padded)
__device__ float g_Nx[BATCH][LEN];    // compacted negative x
__device__ int   g_cnt[BATCH];
__device__ float g_partial[NBLK];
__device__ unsigned g_done = 0;       // self-resetting ticket counter

static __device__ __forceinline__ float sigmoidf(float v) {
    return 1.0f / (1.0f + __expf(-v));
}
static __device__ __forceinline__ float rcpf(float s) {
    float r; asm("rcp.approx.f32 %0, %1;" : "=f"(r) : "f"(s)); return r;
}

// ================= Kernel 1: per-batch parallel compaction -> global lists
__global__ __launch_bounds__(TPB) void compact_kernel(
        const float* __restrict__ inp,
        const int*   __restrict__ tgt,
        const float* __restrict__ freq) {
    const int b = blockIdx.x;
    const int tid = threadIdx.x;
    const int w = tid >> 5, lane = tid & 31;
    __shared__ int s_cntP[NW];

    const int rowoff = b * LEN;

    // Pass A: ballots + value prefetch (16 independent loads in flight)
    unsigned bal[KPW];
    float    xv[KPW];
    int pc = 0;
#pragma unroll
    for (int k = 0; k < KPW; k++) {
        int i = w * CHUNK + k * 32 + lane;
        int t = tgt[rowoff + i];
        xv[k] = inp[rowoff + i];
        bal[k] = __ballot_sync(0xffffffffu, t != 0);
        pc += __popc(bal[k]);
    }
    if (lane == 0) s_cntP[w] = pc;
    __syncthreads();

    int prefP = 0, cp = 0;
#pragma unroll
    for (int ww = 0; ww < NW; ww++) {
        int c = s_cntP[ww];
        if (ww < w) prefP += c;
        cp += c;
    }
    const int prefN = w * CHUNK - prefP;

    // Pass B: scatter compacted values to global
    const unsigned lt = (1u << lane) - 1u;
    int baseP = 0, baseN = 0;
#pragma unroll
    for (int k = 0; k < KPW; k++) {
        int i = w * CHUNK + k * 32 + lane;
        float x = sigmoidf(xv[k]);
        unsigned m = bal[k];
        if ((m >> lane) & 1u) {
            int pos = prefP + baseP + __popc(m & lt);
            g_Px[b][pos] = x;
            g_Pf[b][pos] = freq[i];
        } else {
            int pos = prefN + baseN + (lane - __popc(m & lt));
            g_Nx[b][pos] = x;
        }
        int c = __popc(m);
        baseP += c;
        baseN += 32 - c;
    }
    // Zero-pad positive lists so pair kernel can load unguarded
    for (int i = cp + tid; i < LEN; i += TPB) {
        g_Px[b][i] = 0.0f;
        g_Pf[b][i] = 0.0f;
    }
    if (tid == 0) g_cnt[b] = cp;
}

// ---- One register-blocked pass over KR*256 a-lanes vs the block's j-window.
// PP part is triangular (a < s_j only; result doubled by caller epilogue):
// per-lane start m0 since window slots s = jt + JT*m are increasing in m.
// Zero-padding makes out-of-range loads safe; GUARD zeroes pad-lane results.
template <int KR, bool GUARD>
static __device__ __forceinline__ float pair_pass(
        const float*  __restrict__ sPx, const float* __restrict__ sPf,
        const float4* __restrict__ wPP, const float* __restrict__ wNx,
        int nP, int nN, int abase, int tid, int cp, int jt) {
    float xa[KR], fa[KR], accN[KR], accP[KR];
#pragma unroll
    for (int k = 0; k < KR; k++) {
        int ai = abase + tid + k * TPB;
        xa[k] = sPx[ai]; fa[k] = sPf[ai];
        accN[k] = 0.0f; accP[k] = 0.0f;
    }

    // PP: per-k triangular loops (lanes within a warp differ in m0 by <=1)
#pragma unroll
    for (int k = 0; k < KR; k++) {
        int a = abase + tid + k * TPB;
        int m0 = (a >= jt) ? ((a - jt) / JT + 1) : 0;
        float xk = xa[k], fk = fa[k], acc = 0.0f;
#pragma unroll 2
        for (int j = m0; j < nP; j++) {
            float4 t = wPP[j];                // (-x_s, -f_s, f_s)
            float d  = xk + t.x;              // x_a - x_s
            float fd = fk + t.y;              // f_a - f_s
            float s  = fk + t.z;              // f_a + f_s > 0
            acc = fmaf(fmaxf(fd * d, 0.0f), rcpf(s), acc);
        }
        accP[k] = acc;
    }

    // PN: full window, KR-amortized broadcast
#pragma unroll 4
    for (int j = 0; j < nN; j++) {
        float xj = wNx[j];
#pragma unroll
        for (int k = 0; k < KR; k++)
            accN[k] += fmaxf(xj - xa[k], 0.0f);   // relu(x_j - x_a), C=0
    }

    float tot = 0.0f;
#pragma unroll
    for (int k = 0; k < KR; k++) {
        float v = fmaf(2.0f, accP[k], GAMMA * accN[k]);   // double triangle
        if (GUARD) v *= (abase + tid + k * TPB < cp) ? 1.0f : 0.0f;
        tot += v;
    }
    return tot;
}

// ================= Kernel 2: pairwise loss + fused deterministic reduction
__global__ __launch_bounds__(TPB, 5) void pair_kernel(float* __restrict__ out,
                                                      int out_size) {
    const int jt  = blockIdx.x;
    const int b   = blockIdx.y;
    const int tid = threadIdx.x;

    __shared__ float  sPx[LEN];
    __shared__ float  sPf[LEN];
    __shared__ float4 wPP[MAXM];   // (-x_s, -f_s, f_s, 0) for positive j-slots
    __shared__ float  wNx[MAXM];   // x_j for negative j-slots
    __shared__ float  red[TPB];
    __shared__ int    s_last;

    const int cp = g_cnt[b];
    const int cpR = ((cp + TPB - 1) / TPB) * TPB;   // <= LEN (pad zeros exist)

    // Load compacted a-lists into smem (zero-padded region included)
    for (int i = tid; i < cpR; i += TPB) {
        sPx[i] = g_Px[b][i];
        sPf[i] = g_Pf[b][i];
    }

    // Gather this block's strided j-slot window: s = jt + JT*m over [P|N]
    const int M = (LEN - 1 - jt) / JT + 1;
    int mP = 0;
    if (cp > jt) { mP = (cp - jt + JT - 1) / JT; if (mP > M) mP = M; }
    for (int m = tid; m < M; m += TPB) {
        int s = jt + JT * m;
        if (m < mP) {
            float x = g_Px[b][s], f = g_Pf[b][s];
            wPP[m] = make_float4(-x, -f, f, 0.0f);
        } else {
            wNx[m - mP] = g_Nx[b][s - cp];
        }
    }
    __syncthreads();
    const int nP = mP, nN = M - mP;

    float total = 0.0f;

    // Full unguarded KR=4 passes while more than 5*TPB a's remain
    int abase = 0, rem = cp;
    while (rem > 5 * TPB) {
        total += pair_pass<4, false>(sPx, sPf, wPP, wNx, nP, nN, abase, tid, cp, jt);
        abase += 4 * TPB;
        rem   -= 4 * TPB;
    }
    // One guarded adaptive pass covers the remainder (rem in 1..1280)
    switch ((rem + TPB - 1) / TPB) {
        case 1: total += pair_pass<1, true>(sPx, sPf, wPP, wNx, nP, nN, abase, tid, cp, jt); break;
        case 2: total += pair_pass<2, true>(sPx, sPf, wPP, wNx, nP, nN, abase, tid, cp, jt); break;
        case 3: total += pair_pass<3, true>(sPx, sPf, wPP, wNx, nP, nN, abase, tid, cp, jt); break;
        case 4: total += pair_pass<4, true>(sPx, sPf, wPP, wNx, nP, nN, abase, tid, cp, jt); break;
        case 5: total += pair_pass<5, true>(sPx, sPf, wPP, wNx, nP, nN, abase, tid, cp, jt); break;
        default: break;   // rem == 0
    }

    // ---- Deterministic in-block tree reduction
    red[tid] = total;
    __syncthreads();
    for (int s = TPB / 2; s > 0; s >>= 1) {
        if (tid < s) red[tid] += red[tid + s];
        __syncthreads();
    }
    if (tid == 0) g_partial[b * JT + jt] = red[0];

    // ---- Fused final reduction: last block sums all partials in fixed order
    __threadfence();
    if (tid == 0) {
        unsigned old = atomicAdd(&g_done, 1u);
        s_last = (old == NBLK - 1) ? 1 : 0;
    }
    __syncthreads();
    if (s_last) {
        float s = 0.0f;
        for (int i = tid; i < NBLK; i += TPB) s += g_partial[i];
        red[tid] = s;
        __syncthreads();
        for (int st = TPB / 2; st > 0; st >>= 1) {
            if (tid < st) red[tid] += red[tid + st];
            __syncthreads();
        }
        if (tid == 0) {
            float r = red[0] / (float)BATCH;
            for (int i = 0; i < out_size; i++) out[i] = r;
            g_done = 0;                 // self-reset for graph replay
        }
    }
}

extern "C" void kernel_launch(void* const* d_in, const int* in_sizes, int n_in,
                              void* d_out, int out_size) {
    const float* inp  = (const float*)d_in[0];   // [16, 2048] f32
    const int*   tgt  = (const int*)d_in[1];     // [16, 2048] i32
    const float* freq = (const float*)d_in[2];   // [2048] f32
    float* out = (float*)d_out;

    compact_kernel<<<BATCH, TPB>>>(inp, tgt, freq);
    pair_kernel<<<dim3(JT, BATCH), TPB>>>(out, out_size);
}

// round 9
// speedup vs baseline: 1.5392x; 1.5392x over previous
#include <cuda_runtime.h>
#include <cuda_bf16.h>

#define BATCH 16
#define LEN   2048
#define JT    37              // 37*16 = 592 = 148*4 blocks -> one even wave
#define TPB   256
#define NW    8
#define CHUNK 256             // elements per warp in compaction
#define KPW   8               // ballot sub-iterations per warp
#define GAMMA 0.1f
#define MAXM  56              // max j-slots per block
#define NBLK  (BATCH * JT)

__device__ float g_partial[NBLK];
__device__ unsigned g_done = 0;       // self-resetting ticket counter

static __device__ __forceinline__ float sigmoidf(float v) {
    return 1.0f / (1.0f + __expf(-v));
}
static __device__ __forceinline__ float rcpf(float s) {
    float r; asm("rcp.approx.f32 %0, %1;" : "=f"(r) : "f"(s)); return r;
}

// One register-blocked pass over KR*256 a-lanes vs the block's j-window.
// PN uses the max identity: sum_j relu(xj-xa) = sum_j max(xj,xa) - nN*xa
// (2 slots/pair instead of 3). Zero-padded lists make loads safe; GUARD
// zeroes pad-lane results.
template <int KR, bool GUARD>
static __device__ __forceinline__ float pair_pass(
        const float*  __restrict__ sPx, const float* __restrict__ sPf,
        const float4* __restrict__ wPP, const float* __restrict__ wNx,
        int nP, int nN, int abase, int tid, int cp) {
    float xa[KR], fa[KR], accP[KR], accM[KR];
#pragma unroll
    for (int k = 0; k < KR; k++) {
        int ai = abase + tid + k * TPB;
        xa[k] = sPx[ai]; fa[k] = sPf[ai];
        accP[k] = 0.0f; accM[k] = 0.0f;
    }
#pragma unroll 4
    for (int j = 0; j < nP; j++) {
        float4 t = wPP[j];                    // 1 LDS.128 amortized over KR lanes
#pragma unroll
        for (int k = 0; k < KR; k++) {
            float d  = xa[k] + t.x;           // x_a - x_j
            float fd = fa[k] + t.y;           // f_a - f_j
            float s  = fa[k] + t.z;           // f_a + f_j > 0
            accP[k] = fmaf(fmaxf(fd * d, 0.0f), rcpf(s), accP[k]);
        }
    }
#pragma unroll 4
    for (int j = 0; j < nN; j++) {
        float xj = wNx[j];
#pragma unroll
        for (int k = 0; k < KR; k++)
            accM[k] += fmaxf(xj, xa[k]);      // FMNMX + FADD only
    }
    float tot = 0.0f;
    const float fnN = (float)nN;
#pragma unroll
    for (int k = 0; k < KR; k++) {
        float pn = fmaf(-fnN, xa[k], accM[k]);      // = sum relu(xj - xa)
        float v  = fmaf(GAMMA, pn, accP[k]);
        if (GUARD) v *= (abase + tid + k * TPB < cp) ? 1.0f : 0.0f;
        tot += v;
    }
    return tot;
}

// ============ Single fused kernel: compact -> pairs -> global reduction
__global__ __launch_bounds__(TPB, 4) void fused_kernel(
        const float* __restrict__ inp,
        const int*   __restrict__ tgt,
        const float* __restrict__ freq,
        float* __restrict__ out, int out_size) {
    const int jt  = blockIdx.x;
    const int b   = blockIdx.y;
    const int tid = threadIdx.x;
    const int w   = tid >> 5, lane = tid & 31;

    __shared__ float  sPx[LEN];
    __shared__ float  sPf[LEN];
    __shared__ float  sNx[LEN];
    __shared__ int    s_cntP[NW];
    __shared__ float4 wPP[MAXM];   // (-x_s, -f_s, f_s, 0) positive window slots
    __shared__ float  wNx[MAXM];   // x_j negative window slots
    __shared__ float  red[TPB];
    __shared__ int    s_last;

    const int rowoff = b * LEN;

    // ---- Compaction pass A: ballots + value prefetch (16 loads in flight)
    unsigned bal[KPW];
    float    xv[KPW];
    int pc = 0;
#pragma unroll
    for (int k = 0; k < KPW; k++) {
        int i = w * CHUNK + k * 32 + lane;
        int t = tgt[rowoff + i];
        xv[k] = inp[rowoff + i];
        bal[k] = __ballot_sync(0xffffffffu, t != 0);
        pc += __popc(bal[k]);
    }
    if (lane == 0) s_cntP[w] = pc;
    __syncthreads();

    int prefP = 0, cp = 0;
#pragma unroll
    for (int ww = 0; ww < NW; ww++) {
        int c = s_cntP[ww];
        if (ww < w) prefP += c;
        cp += c;
    }
    const int prefN = w * CHUNK - prefP;

    // ---- Compaction pass B: scatter into shared lists
    const unsigned lt = (1u << lane) - 1u;
    int baseP = 0, baseN = 0;
#pragma unroll
    for (int k = 0; k < KPW; k++) {
        int i = w * CHUNK + k * 32 + lane;
        float x = sigmoidf(xv[k]);
        unsigned m = bal[k];
        if ((m >> lane) & 1u) {
            int pos = prefP + baseP + __popc(m & lt);
            sPx[pos] = x;
            sPf[pos] = freq[i];
        } else {
            int pos = prefN + baseN + (lane - __popc(m & lt));
            sNx[pos] = x;
        }
        int c = __popc(m);
        baseP += c;
        baseN += 32 - c;
    }
    const int cpR = ((cp + TPB - 1) / TPB) * TPB;
    // Zero-pad positives up to pass granularity (disjoint from scatter region)
    for (int i = cp + tid; i < cpR + TPB && i < LEN; i += TPB) {
        sPx[i] = 0.0f;
        sPf[i] = 0.0f;
    }
    __syncthreads();

    // ---- Gather this block's strided j-window: slots s = jt + JT*m over [P|N]
    const int M = (LEN - 1 - jt) / JT + 1;
    int mP = 0;
    if (cp > jt) { mP = (cp - jt + JT - 1) / JT; if (mP > M) mP = M; }
    for (int m = tid; m < M; m += TPB) {
        int s = jt + JT * m;
        if (m < mP) {
            float x = sPx[s], f = sPf[s];
            wPP[m] = make_float4(-x, -f, f, 0.0f);
        } else {
            wNx[m - mP] = sNx[s - cp];
        }
    }
    __syncthreads();
    const int nP = mP, nN = M - mP;

    float total = 0.0f;

    // Full unguarded KR=4 passes while more than 5*TPB a's remain
    int abase = 0, rem = cp;
    while (rem > 5 * TPB) {
        total += pair_pass<4, false>(sPx, sPf, wPP, wNx, nP, nN, abase, tid, cp);
        abase += 4 * TPB;
        rem   -= 4 * TPB;
    }
    // One guarded adaptive pass covers the remainder (rem in 1..1280)
    switch ((rem + TPB - 1) / TPB) {
        case 1: total += pair_pass<1, true>(sPx, sPf, wPP, wNx, nP, nN, abase, tid, cp); break;
        case 2: total += pair_pass<2, true>(sPx, sPf, wPP, wNx, nP, nN, abase, tid, cp); break;
        case 3: total += pair_pass<3, true>(sPx, sPf, wPP, wNx, nP, nN, abase, tid, cp); break;
        case 4: total += pair_pass<4, true>(sPx, sPf, wPP, wNx, nP, nN, abase, tid, cp); break;
        case 5: total += pair_pass<5, true>(sPx, sPf, wPP, wNx, nP, nN, abase, tid, cp); break;
        default: break;   // rem == 0
    }

    // ---- Deterministic in-block tree reduction
    red[tid] = total;
    __syncthreads();
    for (int s = TPB / 2; s > 0; s >>= 1) {
        if (tid < s) red[tid] += red[tid + s];
        __syncthreads();
    }
    if (tid == 0) g_partial[b * JT + jt] = red[0];

    // ---- Fused final reduction: last block sums all partials in fixed order
    __threadfence();
    if (tid == 0) {
        unsigned old = atomicAdd(&g_done, 1u);
        s_last = (old == NBLK - 1) ? 1 : 0;
    }
    __syncthreads();
    if (s_last) {
        float s = 0.0f;
        for (int i = tid; i < NBLK; i += TPB) s += g_partial[i];
        red[tid] = s;
        __syncthreads();
        for (int st = TPB / 2; st > 0; st >>= 1) {
            if (tid < st) red[tid] += red[tid + st];
            __syncthreads();
        }
        if (tid == 0) {
            float r = red[0] / (float)BATCH;
            for (int i = 0; i < out_size; i++) out[i] = r;
            g_done = 0;                 // self-reset for graph replay
        }
    }
}

extern "C" void kernel_launch(void* const* d_in, const int* in_sizes, int n_in,
                              void* d_out, int out_size) {
    const float* inp  = (const float*)d_in[0];   // [16, 2048] f32
    const int*   tgt  = (const int*)d_in[1];     // [16, 2048] i32
    const float* freq = (const float*)d_in[2];   // [2048] f32
    float* out = (float*)d_out;

    fused_kernel<<<dim3(JT, BATCH), TPB>>>(inp, tgt, freq, out, out_size);
}